// round 6
// baseline (speedup 1.0000x reference)
#include <cuda_runtime.h>

#define GG    4096
#define MM    50
#define KK    30
#define HH    32
#define FIN   128
#define EPG   400      // edges per graph
#define DLAT  97
#define DDENSE 352
#define NN    (GG * MM)

// ---- static device scratch (no allocs allowed) ----
__device__ float  g_t[(size_t)NN * HH];        // GEMM output (t0/t1/t2, reused)
__device__ float  g_h[(size_t)NN * HH];        // post-agg hidden (h1/h2/h3, reused)
__device__ float  g_lat[(size_t)NN * DLAT];    // concat latent, cols 0..95 (col 96 kept local)
__device__ float2 g_epack[(size_t)GG * EPG];   // (src_local_bits, norm) CSR by dst
__device__ int    g_rp[(size_t)GG * (MM + 1)];
__device__ float  g_snorm[(size_t)NN];         // dinv[n]^2 (self-loop weight)
__device__ float  g_z[(size_t)GG * DDENSE];

// ---------------------------------------------------------------------------
// prep: per-graph GCN normalization + CSR (grouped by dst), persisted to global
// ---------------------------------------------------------------------------
__global__ void __launch_bounds__(256)
prep_kernel(const int* __restrict__ ei, int E) {
    __shared__ int   cnt[MM], cnt2[MM], rp[MM + 1];
    __shared__ float dinv[MM];
    __shared__ int   es[EPG], ed[EPG];
    const int tid = threadIdx.x, lane = tid & 31, warp = tid >> 5;
    const int g = blockIdx.x;

    if (tid < MM) { cnt[tid] = 1; cnt2[tid] = 0; }   // self loop
    const int ebase = g * EPG;
    for (int e = tid; e < EPG; e += 256) {
        es[e] = ei[ebase + e] - g * MM;
        ed[e] = ei[E + ebase + e] - g * MM;
    }
    __syncthreads();

    for (int e = tid; e < EPG; e += 256) atomicAdd(&cnt[ed[e]], 1);
    __syncthreads();

    if (tid < MM) dinv[tid] = rsqrtf((float)cnt[tid]);
    if (warp == 0) {   // exclusive scan of (cnt-1) over 50 nodes
        int a = (lane < MM) ? (cnt[lane] - 1) : 0;
        int b = (lane + 32 < MM) ? (cnt[lane + 32] - 1) : 0;
        int sa = a, sb = b;
#pragma unroll
        for (int o = 1; o < 32; o <<= 1) {
            int ta = __shfl_up_sync(0xffffffffu, sa, o);
            int tb = __shfl_up_sync(0xffffffffu, sb, o);
            if (lane >= o) { sa += ta; sb += tb; }
        }
        int tot_a = __shfl_sync(0xffffffffu, sa, 31);
        rp[lane] = sa - a;
        if (lane + 32 < MM) rp[lane + 32] = tot_a + sb - b;
        if (lane == 31) rp[MM] = tot_a + sb;
    }
    __syncthreads();

    for (int e = tid; e < EPG; e += 256) {
        int d = ed[e], sl = es[e];
        int pos = rp[d] + atomicAdd(&cnt2[d], 1);
        g_epack[(size_t)g * EPG + pos] =
            make_float2(__int_as_float(sl), dinv[sl] * dinv[d]);
    }
    if (tid <= MM) g_rp[g * (MM + 1) + tid] = rp[tid];
    if (tid < MM)  g_snorm[(size_t)g * MM + tid] = dinv[tid] * dinv[tid];
}

// ---------------------------------------------------------------------------
// batched GEMM: out[N,32] = in[N,KD] @ W[KD,32]. 64 rows/CTA, smem-staged input.
// ---------------------------------------------------------------------------
template <int KD>
__global__ void __launch_bounds__(256)
gemm_kernel(const float* __restrict__ in, const float* __restrict__ W,
            float* __restrict__ out) {
    __shared__ __align__(16) float xs[64 * KD];
    const int tid = threadIdx.x, lane = tid & 31, warp = tid >> 5;
    const size_t base = (size_t)blockIdx.x * 64;

    {   // coalesced float4 staging: huge MLP -> DRAM-BW bound
        const float4* s = reinterpret_cast<const float4*>(in + base * KD);
        float4* d = reinterpret_cast<float4*>(xs);
#pragma unroll
        for (int i = tid; i < 64 * KD / 4; i += 256) d[i] = s[i];
    }
    __syncthreads();

    float acc[8] = {0.f, 0.f, 0.f, 0.f, 0.f, 0.f, 0.f, 0.f};
    const float* xr = xs + warp * 8 * KD;
#pragma unroll 4
    for (int k = 0; k < KD; k += 4) {
        float wa = __ldg(&W[(k + 0) * HH + lane]);
        float wb = __ldg(&W[(k + 1) * HH + lane]);
        float wc = __ldg(&W[(k + 2) * HH + lane]);
        float wd = __ldg(&W[(k + 3) * HH + lane]);
#pragma unroll
        for (int j = 0; j < 8; j++) {
            float4 xv = *reinterpret_cast<const float4*>(&xr[j * KD + k]);
            acc[j] = fmaf(xv.x, wa, fmaf(xv.y, wb, fmaf(xv.z, wc, fmaf(xv.w, wd, acc[j]))));
        }
    }
    float* o = out + (base + (size_t)warp * 8) * HH + lane;
#pragma unroll
    for (int j = 0; j < 8; j++) o[j * HH] = acc[j];
}

// ---------------------------------------------------------------------------
// aggregation: h = tanh(agg(t) + b), also scatter into lat[:, coloff:coloff+32].
// 1 warp per half-graph (nodes n = half, half+2, ...), 4 graphs / CTA.
// ---------------------------------------------------------------------------
__global__ void __launch_bounds__(256)
agg_kernel(const float* __restrict__ t, const float* __restrict__ b,
           float* __restrict__ h, float* __restrict__ lat, int coloff) {
    const int lane = threadIdx.x & 31, warp = threadIdx.x >> 5;
    const int gid = blockIdx.x * 4 + (warp >> 1);
    const int half = warp & 1;
    const size_t nb = (size_t)gid * MM;
    const float2* ep = g_epack + (size_t)gid * EPG;
    const int* rp = g_rp + gid * (MM + 1);
    const float* tg = t + nb * HH;
    const float bias = __ldg(&b[lane]);

    for (int n = half; n < MM; n += 2) {
        float a = tg[n * HH + lane] * __ldg(&g_snorm[nb + n]);
        int e0 = __ldg(&rp[n]), e1 = __ldg(&rp[n + 1]);
        for (int e = e0; e < e1; e++) {
            float2 p = __ldg(&ep[e]);
            a = fmaf(tg[__float_as_int(p.x) * HH + lane], p.y, a);
        }
        float r = tanhf(a + bias);
        h[(nb + n) * HH + lane] = r;
        lat[(nb + n) * DLAT + coloff + lane] = r;
    }
}

// ---------------------------------------------------------------------------
// final per-graph kernel: layer4 + sort-pool + conv1 + maxpool + conv2 -> g_z
// ---------------------------------------------------------------------------
struct FSmem {
    alignas(16) float h3s[MM * HH];       // 6400
    alignas(16) float lat30[KK * 96];     // 11520 (cols 0..95 of selected rows)
    float2 ep[EPG];                       // 3200
    float  z1[16 * KK];                   // 1920
    float  pooled[16 * 15];               // 960
    float  tmp[MM];
    float  h4v[MM];
    float  snorm[MM];
    int    rp[MM + 1];
    int    sel[KK];
};

__global__ void __launch_bounds__(256)
final_kernel(const float* __restrict__ h3, const float* __restrict__ W3,
             const float* __restrict__ b3,
             const float* __restrict__ C1w, const float* __restrict__ C1b,
             const float* __restrict__ C2w, const float* __restrict__ C2b) {
    __shared__ FSmem s;
    const int tid = threadIdx.x, lane = tid & 31, warp = tid >> 5;
    const int g = blockIdx.x;
    const size_t nb = (size_t)g * MM;

    // stage h3 slice + CSR + snorm
    {
        const float4* src = reinterpret_cast<const float4*>(h3 + nb * HH);
        float4* dst = reinterpret_cast<float4*>(s.h3s);
        for (int i = tid; i < MM * HH / 4; i += 256) dst[i] = src[i];
    }
    for (int e = tid; e < EPG; e += 256) s.ep[e] = __ldg(&g_epack[(size_t)g * EPG + e]);
    if (tid <= MM) s.rp[tid] = g_rp[g * (MM + 1) + tid];
    if (tid < MM)  s.snorm[tid] = g_snorm[nb + tid];
    __syncthreads();

    // t3[n] = h3[n] . W3
    {
        float w3 = __ldg(&W3[lane]);
        int n0 = warp * 7;
#pragma unroll
        for (int j = 0; j < 7; j++) {
            int n = n0 + j;
            if (n < MM) {
                float v = s.h3s[n * HH + lane] * w3;
#pragma unroll
                for (int o = 16; o; o >>= 1) v += __shfl_xor_sync(0xffffffffu, v, o);
                if (lane == 0) s.tmp[n] = v;
            }
        }
    }
    __syncthreads();

    // h4 = tanh(agg(t3) + b3)
    if (tid < MM) {
        int n = tid;
        float a = s.tmp[n] * s.snorm[n];
        int e1 = s.rp[n + 1];
        for (int e = s.rp[n]; e < e1; e++) {
            float2 p = s.ep[e];
            a = fmaf(s.tmp[__float_as_int(p.x)], p.y, a);
        }
        s.h4v[n] = tanhf(a + __ldg(&b3[0]));
    }
    __syncthreads();

    // sort-pool: exact rank == stable argsort(-h4)
    if (tid < MM) {
        float vi = s.h4v[tid];
        int r = 0;
        for (int j = 0; j < MM; j++) {
            float vj = s.h4v[j];
            r += (vj > vi) || (vj == vi && j < tid);
        }
        if (r < KK) s.sel[r] = tid;
    }
    __syncthreads();

    // gather selected lat rows (cols 0..95) into smem
    for (int idx = tid; idx < KK * 96; idx += 256) {
        int t = idx / 96, d = idx % 96;
        s.lat30[t * 96 + d] = __ldg(&g_lat[(nb + s.sel[t]) * DLAT + d]);
    }
    __syncthreads();

    // conv1 (per-slot 97-dot; d=96 term from h4v) + relu
    for (int o = tid; o < 16 * KK; o += 256) {
        int t = o % KK, c = o / KK;
        const float* lr = &s.lat30[t * 96];
        const float* cw = &C1w[c * DLAT];
        float a = __ldg(&C1b[c]);
#pragma unroll 4
        for (int d = 0; d < 96; d++) a = fmaf(lr[d], __ldg(&cw[d]), a);
        a = fmaf(s.h4v[s.sel[t]], __ldg(&cw[96]), a);
        s.z1[c * KK + t] = fmaxf(a, 0.f);
    }
    __syncthreads();

    // maxpool(2,2)
    if (tid < 16 * 15) {
        int u = tid % 15, c = tid / 15;
        s.pooled[c * 15 + u] = fmaxf(s.z1[c * KK + 2 * u], s.z1[c * KK + 2 * u + 1]);
    }
    __syncthreads();

    // conv2 (16->32, k=5) + relu
    for (int o2 = tid; o2 < DDENSE; o2 += 256) {
        int o = o2 / 11, u = o2 % 11;
        float a = __ldg(&C2b[o]);
#pragma unroll
        for (int i = 0; i < 16; i++) {
            const float* pw = &C2w[(o * 16 + i) * 5];
            const float* pp = &s.pooled[i * 15 + u];
#pragma unroll
            for (int k2 = 0; k2 < 5; k2++) a = fmaf(pp[k2], __ldg(&pw[k2]), a);
        }
        g_z[(size_t)g * DDENSE + o2] = fmaxf(a, 0.f);
    }
}

// ---------------------------------------------------------------------------
// fused dense: relu(z @ L1w + L1b) @ L2w + L2b. 8 graphs/CTA, 128 threads.
// ---------------------------------------------------------------------------
__global__ void __launch_bounds__(128)
dense_kernel(const float* __restrict__ L1w, const float* __restrict__ L1b,
             const float* __restrict__ L2w, const float* __restrict__ L2b,
             float* __restrict__ out) {
    __shared__ __align__(16) float zs[8][DDENSE];
    __shared__ float red[4][8];
    const int tid = threadIdx.x, lane = tid & 31, warp = tid >> 5;
    const int gbase = blockIdx.x * 8;

    {
        const float4* zsrc = reinterpret_cast<const float4*>(&g_z[(size_t)gbase * DDENSE]);
        float4* zdst = reinterpret_cast<float4*>(&zs[0][0]);
        for (int i = tid; i < 8 * DDENSE / 4; i += 128) zdst[i] = zsrc[i];
    }
    __syncthreads();

    const int ch = warp * 32 + lane;
    float acc[8];
    float l1b = __ldg(&L1b[ch]);
#pragma unroll
    for (int j = 0; j < 8; j++) acc[j] = l1b;

#pragma unroll 2
    for (int d = 0; d < DDENSE; d += 4) {
        float w0 = __ldg(&L1w[(d + 0) * 128 + ch]);
        float w1 = __ldg(&L1w[(d + 1) * 128 + ch]);
        float w2 = __ldg(&L1w[(d + 2) * 128 + ch]);
        float w3 = __ldg(&L1w[(d + 3) * 128 + ch]);
#pragma unroll
        for (int j = 0; j < 8; j++) {
            float4 zv = *reinterpret_cast<const float4*>(&zs[j][d]);
            acc[j] = fmaf(zv.x, w0, fmaf(zv.y, w1, fmaf(zv.z, w2, fmaf(zv.w, w3, acc[j]))));
        }
    }

    float w2v = __ldg(&L2w[ch]);
#pragma unroll
    for (int j = 0; j < 8; j++) {
        float p = fmaxf(acc[j], 0.f) * w2v;
#pragma unroll
        for (int o = 16; o; o >>= 1) p += __shfl_xor_sync(0xffffffffu, p, o);
        if (lane == 0) red[warp][j] = p;
    }
    __syncthreads();

    if (tid < 8) {
        out[gbase + tid] = red[0][tid] + red[1][tid] + red[2][tid] + red[3][tid]
                         + __ldg(&L2b[0]);
    }
}

extern "C" void kernel_launch(void* const* d_in, const int* in_sizes, int n_in,
                              void* d_out, int out_size) {
    const float* x   = (const float*)d_in[0];
    const int*   ei  = (const int*)d_in[1];
    // d_in[2] = batch (unused; graphs are contiguous equal-size blocks)
    const float* W0  = (const float*)d_in[3];
    const float* b0  = (const float*)d_in[4];
    const float* W1  = (const float*)d_in[5];
    const float* b1  = (const float*)d_in[6];
    const float* W2  = (const float*)d_in[7];
    const float* b2  = (const float*)d_in[8];
    const float* W3  = (const float*)d_in[9];
    const float* b3  = (const float*)d_in[10];
    const float* C1w = (const float*)d_in[11];
    const float* C1b = (const float*)d_in[12];
    const float* C2w = (const float*)d_in[13];
    const float* C2b = (const float*)d_in[14];
    const float* L1w = (const float*)d_in[15];
    const float* L1b = (const float*)d_in[16];
    const float* L2w = (const float*)d_in[17];
    const float* L2b = (const float*)d_in[18];

    const int E = in_sizes[1] / 2;

    float *t, *h, *lat;
    cudaGetSymbolAddress((void**)&t,   g_t);
    cudaGetSymbolAddress((void**)&h,   g_h);
    cudaGetSymbolAddress((void**)&lat, g_lat);

    prep_kernel<<<GG, 256>>>(ei, E);
    gemm_kernel<FIN><<<NN / 64, 256>>>(x, W0, t);
    agg_kernel<<<GG / 4, 256>>>(t, b0, h, lat, 0);
    gemm_kernel<HH><<<NN / 64, 256>>>(h, W1, t);
    agg_kernel<<<GG / 4, 256>>>(t, b1, h, lat, 32);
    gemm_kernel<HH><<<NN / 64, 256>>>(h, W2, t);
    agg_kernel<<<GG / 4, 256>>>(t, b2, h, lat, 64);
    final_kernel<<<GG, 256>>>(h, W3, b3, C1w, C1b, C2w, C2b);
    dense_kernel<<<GG / 8, 128>>>(L1w, L1b, L2w, L2b, (float*)d_out);
}

// round 7
// speedup vs baseline: 2.9412x; 2.9412x over previous
#include <cuda_runtime.h>

#define GG    4096
#define MM    50
#define KK    30
#define HH    32
#define FIN   128
#define EPG   400      // edges per graph
#define DLAT  97
#define DDENSE 352
#define NN    (GG * MM)

// static device scratch (no allocs allowed)
__device__ float g_t0[(size_t)NN * HH];   // x @ W0
__device__ float g_z[(size_t)GG * DDENSE];

// ---------------------------------------------------------------------------
// Kernel A: t0 = x @ W0 ([N,128] @ [128,32]). 64 rows/CTA, smem-staged input
// (coalesced float4 staging -> huge MLP -> DRAM-BW bound, not latency bound).
// ---------------------------------------------------------------------------
__global__ void __launch_bounds__(256)
xw0_kernel(const float* __restrict__ x, const float* __restrict__ W0,
           float* __restrict__ t0) {
    __shared__ __align__(16) float xs[64 * FIN];   // 32 KB
    const int tid = threadIdx.x, lane = tid & 31, warp = tid >> 5;
    const size_t base = (size_t)blockIdx.x * 64;

    {
        const float4* s = reinterpret_cast<const float4*>(x + base * FIN);
        float4* d = reinterpret_cast<float4*>(xs);
#pragma unroll
        for (int i = tid; i < 64 * FIN / 4; i += 256) d[i] = s[i];
    }
    __syncthreads();

    float acc[8] = {0.f, 0.f, 0.f, 0.f, 0.f, 0.f, 0.f, 0.f};
    const float* xr = xs + warp * 8 * FIN;
#pragma unroll 4
    for (int k = 0; k < FIN; k += 4) {
        float wa = __ldg(&W0[(k + 0) * HH + lane]);
        float wb = __ldg(&W0[(k + 1) * HH + lane]);
        float wc = __ldg(&W0[(k + 2) * HH + lane]);
        float wd = __ldg(&W0[(k + 3) * HH + lane]);
#pragma unroll
        for (int j = 0; j < 8; j++) {
            float4 xv = *reinterpret_cast<const float4*>(&xr[j * FIN + k]);
            acc[j] = fmaf(xv.x, wa, fmaf(xv.y, wb, fmaf(xv.z, wc, fmaf(xv.w, wd, acc[j]))));
        }
    }
    float* o = t0 + (base + (size_t)warp * 8) * HH + lane;
#pragma unroll
    for (int j = 0; j < 8; j++) o[j * HH] = acc[j];
}

// ---------------------------------------------------------------------------
// Kernel B: per-graph GCN agg1 + layers 2-4 + sort-pool + conv1/conv2
// NOTE: float4-accessed arrays (h, tmp) must sit at 16B-aligned offsets.
// ---------------------------------------------------------------------------
struct Smem {
    alignas(16) float  h[MM * HH];     // 6400  : hidden state (post-tanh)
    alignas(16) float  tmp[MM * HH];   // 6400  : h @ W pre-agg / t0 slice
    float2 epack[EPG];                 // 3200  : (src_bits, norm) CSR by dst
    float  lat[MM * DLAT];             // 19400 : concat[h1..h4] (scalar access)
    float  z1[16 * KK];                // 1920
    float  pooled[16 * 15];            // 960
    float  dinv[MM];
    float  h4v[MM];
    int    rp[MM + 1];
    int    cnt[MM];                    // degree counter (init 1 = self loop)
    int    cnt2[MM];                   // scatter cursor
    int    sel[KK];
    int    eraws[EPG];
    int    erawd[EPG];
};

// h[M,32](smem) @ W[32,32](global, L1-hot) -> tmp[M,32]. Warp tile: 7 nodes x 32 ch.
__device__ __forceinline__ void gcn_matmul32(const float* __restrict__ in,
                                             const float* __restrict__ Wg,
                                             float* __restrict__ tmp,
                                             int warp, int lane) {
    int nbase = warp * 7;
    if (nbase >= MM) return;
    int ncnt = MM - nbase; if (ncnt > 7) ncnt = 7;
    float acc[7] = {0.f, 0.f, 0.f, 0.f, 0.f, 0.f, 0.f};
#pragma unroll 4
    for (int k = 0; k < HH; k += 4) {
        float wa = __ldg(&Wg[(k + 0) * HH + lane]);
        float wb = __ldg(&Wg[(k + 1) * HH + lane]);
        float wc = __ldg(&Wg[(k + 2) * HH + lane]);
        float wd = __ldg(&Wg[(k + 3) * HH + lane]);
#pragma unroll
        for (int j = 0; j < 7; j++) {
            if (j < ncnt) {
                float4 xv = *reinterpret_cast<const float4*>(&in[(nbase + j) * HH + k]);
                acc[j] = fmaf(xv.x, wa, fmaf(xv.y, wb, fmaf(xv.z, wc, fmaf(xv.w, wd, acc[j]))));
            }
        }
    }
    for (int j = 0; j < ncnt; j++) tmp[(nbase + j) * HH + lane] = acc[j];
}

// gather-aggregate (CSR by dst) + self loop + bias + tanh -> h and lat column block
__device__ __forceinline__ void gcn_agg(Smem& s, int coloff, float bias,
                                        int warp, int lane) {
    for (int n = warp; n < MM; n += 8) {
        float di = s.dinv[n];
        float a = s.tmp[n * HH + lane] * di * di;
        int e1 = s.rp[n + 1];
        for (int e = s.rp[n]; e < e1; e++) {
            float2 p = s.epack[e];
            a = fmaf(s.tmp[__float_as_int(p.x) * HH + lane], p.y, a);
        }
        float r = tanhf(a + bias);
        s.lat[n * DLAT + coloff + lane] = r;
        s.h[n * HH + lane] = r;
    }
}

__global__ void __launch_bounds__(256, 4)
graph_kernel(const float* __restrict__ t0, const int* __restrict__ ei,
             const float* __restrict__ b0,
             const float* __restrict__ W1, const float* __restrict__ b1,
             const float* __restrict__ W2, const float* __restrict__ b2,
             const float* __restrict__ W3, const float* __restrict__ b3,
             const float* __restrict__ C1w, const float* __restrict__ C1b,
             const float* __restrict__ C2w, const float* __restrict__ C2b,
             int E) {
    extern __shared__ __align__(16) char raw[];
    Smem& s = *reinterpret_cast<Smem*>(raw);
    const int tid = threadIdx.x, lane = tid & 31, warp = tid >> 5;
    const int g = blockIdx.x;

    // ---- stage t0 slice into tmp (coalesced), edges, counters ----
    {
        const float4* tsrc = reinterpret_cast<const float4*>(t0 + (size_t)g * MM * HH);
        float4* tdst = reinterpret_cast<float4*>(s.tmp);
        for (int i = tid; i < MM * HH / 4; i += 256) tdst[i] = tsrc[i];
    }
    if (tid < MM) { s.cnt[tid] = 1; s.cnt2[tid] = 0; }  // self loop in cnt
    const int ebase = g * EPG;
    for (int e = tid; e < EPG; e += 256) {
        s.eraws[e] = ei[ebase + e] - g * MM;
        s.erawd[e] = ei[E + ebase + e] - g * MM;
    }
    __syncthreads();

    // ---- degree count ----
    for (int e = tid; e < EPG; e += 256) atomicAdd(&s.cnt[s.erawd[e]], 1);
    __syncthreads();

    // ---- dinv + warp-parallel exclusive scan of (cnt-1) -> rp ----
    if (tid >= 64 && tid < 64 + MM) s.dinv[tid - 64] = rsqrtf((float)s.cnt[tid - 64]);
    if (warp == 0) {
        int a = (lane < MM) ? (s.cnt[lane] - 1) : 0;
        int b = (lane + 32 < MM) ? (s.cnt[lane + 32] - 1) : 0;
        int sa = a, sb = b;
#pragma unroll
        for (int o = 1; o < 32; o <<= 1) {
            int ta = __shfl_up_sync(0xffffffffu, sa, o);
            int tb = __shfl_up_sync(0xffffffffu, sb, o);
            if (lane >= o) { sa += ta; sb += tb; }
        }
        int tot_a = __shfl_sync(0xffffffffu, sa, 31);
        s.rp[lane] = sa - a;
        if (lane + 32 < MM) s.rp[lane + 32] = tot_a + sb - b;
        if (lane == 31) s.rp[MM] = tot_a + sb;
    }
    __syncthreads();

    // ---- build CSR grouped by dst ----
    for (int e = tid; e < EPG; e += 256) {
        int d = s.erawd[e], sl = s.eraws[e];
        int pos = s.rp[d] + atomicAdd(&s.cnt2[d], 1);
        s.epack[pos] = make_float2(__int_as_float(sl), s.dinv[sl] * s.dinv[d]);
    }
    __syncthreads();

    // ---- layer 1 aggregation (t0 already = x@W0) ----
    gcn_agg(s, 0, __ldg(&b0[lane]), warp, lane);
    __syncthreads();

    // ---- layers 2-3 ----
    gcn_matmul32(s.h, W1, s.tmp, warp, lane);
    __syncthreads();
    gcn_agg(s, 32, __ldg(&b1[lane]), warp, lane);
    __syncthreads();

    gcn_matmul32(s.h, W2, s.tmp, warp, lane);
    __syncthreads();
    gcn_agg(s, 64, __ldg(&b2[lane]), warp, lane);
    __syncthreads();

    // ---- layer 4: H=32 -> 1 ----
    {
        float w3 = __ldg(&W3[lane]);
        for (int n = warp; n < MM; n += 8) {
            float v = s.h[n * HH + lane] * w3;
#pragma unroll
            for (int o = 16; o; o >>= 1) v += __shfl_xor_sync(0xffffffffu, v, o);
            if (lane == 0) s.tmp[n] = v;
        }
    }
    __syncthreads();
    if (tid < MM) {
        int n = tid;
        float di = s.dinv[n];
        float a = s.tmp[n] * di * di;
        int e1 = s.rp[n + 1];
        for (int e = s.rp[n]; e < e1; e++) {
            float2 p = s.epack[e];
            a = fmaf(s.tmp[__float_as_int(p.x)], p.y, a);
        }
        float r = tanhf(a + __ldg(&b3[0]));
        s.lat[n * DLAT + 96] = r;
        s.h4v[n] = r;
    }
    __syncthreads();

    // ---- sort-pool: exact rank == stable argsort(-h4) ----
    if (tid < MM) {
        float vi = s.h4v[tid];
        int r = 0;
        for (int j = 0; j < MM; j++) {
            float vj = s.h4v[j];
            r += (vj > vi) || (vj == vi && j < tid);
        }
        if (r < KK) s.sel[r] = tid;
    }
    __syncthreads();

    // ---- conv1 (per-slot 97-dot) + relu ----
    for (int o = tid; o < 16 * KK; o += 256) {
        int t = o % KK, c = o / KK;
        const float* lr = &s.lat[s.sel[t] * DLAT];
        const float* cw = &C1w[c * DLAT];
        float a = __ldg(&C1b[c]);
#pragma unroll 4
        for (int d = 0; d < DLAT; d++) a = fmaf(lr[d], __ldg(&cw[d]), a);
        s.z1[c * KK + t] = fmaxf(a, 0.f);
    }
    __syncthreads();

    // ---- maxpool(2,2) ----
    if (tid < 16 * 15) {
        int u = tid % 15, c = tid / 15;
        s.pooled[c * 15 + u] = fmaxf(s.z1[c * KK + 2 * u], s.z1[c * KK + 2 * u + 1]);
    }
    __syncthreads();

    // ---- conv2 (16->32, k=5) + relu -> global scratch ----
    for (int o2 = tid; o2 < DDENSE; o2 += 256) {
        int o = o2 / 11, u = o2 % 11;
        float a = __ldg(&C2b[o]);
#pragma unroll
        for (int i = 0; i < 16; i++) {
            const float* pw = &C2w[(o * 16 + i) * 5];
            const float* pp = &s.pooled[i * 15 + u];
#pragma unroll
            for (int k2 = 0; k2 < 5; k2++) a = fmaf(pp[k2], __ldg(&pw[k2]), a);
        }
        g_z[(size_t)g * DDENSE + o2] = fmaxf(a, 0.f);
    }
}

// ---------------------------------------------------------------------------
// Kernel C: fused dense. 8 graphs / CTA, 128 threads, warp = 32 ch x 8 graphs.
// ---------------------------------------------------------------------------
__global__ void __launch_bounds__(128)
dense_kernel(const float* __restrict__ L1w, const float* __restrict__ L1b,
             const float* __restrict__ L2w, const float* __restrict__ L2b,
             float* __restrict__ out) {
    __shared__ __align__(16) float zs[8][DDENSE];
    __shared__ float red[4][8];
    const int tid = threadIdx.x, lane = tid & 31, warp = tid >> 5;
    const int gbase = blockIdx.x * 8;

    {
        const float4* zsrc = reinterpret_cast<const float4*>(&g_z[(size_t)gbase * DDENSE]);
        float4* zdst = reinterpret_cast<float4*>(&zs[0][0]);
        for (int i = tid; i < 8 * DDENSE / 4; i += 128) zdst[i] = zsrc[i];
    }
    __syncthreads();

    const int ch = warp * 32 + lane;
    float acc[8];
    float l1b = __ldg(&L1b[ch]);
#pragma unroll
    for (int j = 0; j < 8; j++) acc[j] = l1b;

#pragma unroll 2
    for (int d = 0; d < DDENSE; d += 4) {
        float w0 = __ldg(&L1w[(d + 0) * 128 + ch]);
        float w1 = __ldg(&L1w[(d + 1) * 128 + ch]);
        float w2 = __ldg(&L1w[(d + 2) * 128 + ch]);
        float w3 = __ldg(&L1w[(d + 3) * 128 + ch]);
#pragma unroll
        for (int j = 0; j < 8; j++) {
            float4 zv = *reinterpret_cast<const float4*>(&zs[j][d]);
            acc[j] = fmaf(zv.x, w0, fmaf(zv.y, w1, fmaf(zv.z, w2, fmaf(zv.w, w3, acc[j]))));
        }
    }

    float w2v = __ldg(&L2w[ch]);
#pragma unroll
    for (int j = 0; j < 8; j++) {
        float p = fmaxf(acc[j], 0.f) * w2v;
#pragma unroll
        for (int o = 16; o; o >>= 1) p += __shfl_xor_sync(0xffffffffu, p, o);
        if (lane == 0) red[warp][j] = p;
    }
    __syncthreads();

    if (tid < 8) {
        out[gbase + tid] = red[0][tid] + red[1][tid] + red[2][tid] + red[3][tid]
                         + __ldg(&L2b[0]);
    }
}

extern "C" void kernel_launch(void* const* d_in, const int* in_sizes, int n_in,
                              void* d_out, int out_size) {
    const float* x   = (const float*)d_in[0];
    const int*   ei  = (const int*)d_in[1];
    // d_in[2] = batch (unused; graphs are contiguous equal-size blocks)
    const float* W0  = (const float*)d_in[3];
    const float* b0  = (const float*)d_in[4];
    const float* W1  = (const float*)d_in[5];
    const float* b1  = (const float*)d_in[6];
    const float* W2  = (const float*)d_in[7];
    const float* b2  = (const float*)d_in[8];
    const float* W3  = (const float*)d_in[9];
    const float* b3  = (const float*)d_in[10];
    const float* C1w = (const float*)d_in[11];
    const float* C1b = (const float*)d_in[12];
    const float* C2w = (const float*)d_in[13];
    const float* C2b = (const float*)d_in[14];
    const float* L1w = (const float*)d_in[15];
    const float* L1b = (const float*)d_in[16];
    const float* L2w = (const float*)d_in[17];
    const float* L2b = (const float*)d_in[18];

    const int E = in_sizes[1] / 2;

    float* t0;
    cudaGetSymbolAddress((void**)&t0, g_t0);

    const int smem = (int)sizeof(Smem);
    cudaFuncSetAttribute(graph_kernel, cudaFuncAttributeMaxDynamicSharedMemorySize, smem);

    xw0_kernel<<<NN / 64, 256>>>(x, W0, t0);
    graph_kernel<<<GG, 256, smem>>>(t0, ei, b0, W1, b1, W2, b2, W3, b3,
                                    C1w, C1b, C2w, C2b, E);
    dense_kernel<<<GG / 8, 128>>>(L1w, L1b, L2w, L2b, (float*)d_out);
}